// round 7
// baseline (speedup 1.0000x reference)
#include <cuda_runtime.h>

// Rules_67619965108887: out[b,s,r] = (a_i*b_j)*c_k, r = i*25+j*5+k,
//   a_i=f(x[i]), b_j=f(x[5+j]), c_k=f(x[10+k]), f(v)=(v==0)?1:v.
// Association (a*b)*c matches jnp.prod ascending order -> bitwise equal.
//
// R7 (= R6 resubmit after infra failure, minor tweaks): all prior variants
// stalled ~7us with no pipe >47% => dependency-stall bound on conflicted smem
// + per-element index math. This design makes EVERY shared access
// conflict-free and EVERY index loop-invariant:
//   Phase 1: coalesced float4 load of 16 positions, zero-fix, scatter to
//            padded sx[p][16].
//   Phase 2: thread t (<125) owns rule r=t for ALL 16 positions. (i,j,k)
//            computed once. In-warp sx loads hit few distinct addresses ->
//            pure broadcast (N=1). Store fired[p*125+t]: dense consecutive
//            -> conflict-free.
//   Phase 3: dense copy fired->gmem: consecutive LDS.128 (conflict-free) +
//            coalesced STG.128 (500 float4 / CTA, 4 per thread).
// 128 thr / 16 pos / CTA, grid 2048, 9KB smem, low regs -> high occupancy,
// fine-grained waves.

constexpr int THREADS   = 128;
constexpr int P_PER_CTA = 16;
constexpr int IN_VEC4   = P_PER_CTA * 15 / 4;     // 60
constexpr int OUT_VEC4  = P_PER_CTA * 125 / 4;    // 500

__global__ __launch_bounds__(THREADS, 12)
void rules_fired_kernel(const float4* __restrict__ x4,
                        float4* __restrict__ out4) {
    __shared__ float sx[P_PER_CTA * 16];                    // 1 KB
    __shared__ __align__(16) float fired[P_PER_CTA * 125];  // 8 KB, dense

    const int t = threadIdx.x;
    const size_t cta = blockIdx.x;

    // ---- Phase 1: coalesced load of 16 positions (240 floats = 60 float4) ----
    if (t < IN_VEC4) {
        float4 v = x4[cta * IN_VEC4 + t];
        float vals[4] = {v.x, v.y, v.z, v.w};
        const int li0 = t * 4;
        #pragma unroll
        for (int e = 0; e < 4; e++) {
            const int li = li0 + e;               // 0..239
            const int p  = li / 15;
            const int f  = li - p * 15;
            const float w = vals[e];
            sx[p * 16 + f] = (w == 0.0f) ? 1.0f : w;
        }
    }
    __syncthreads();

    // ---- Phase 2: thread owns rule r = t for all 16 positions ----
    if (t < 125) {
        const int i  = t / 25;                    // computed ONCE
        const int jj = t - i * 25;
        const int j  = jj / 5;
        const int k  = jj - j * 5;
        const int oa = i;                         // loop-invariant sx offsets
        const int ob = 5 + j;
        const int oc = 10 + k;
        #pragma unroll
        for (int p = 0; p < P_PER_CTA; p++) {
            // p*16 is a compile-time constant per unrolled iteration -> folds
            // into the LDS immediate; loads are warp-broadcast (N=1).
            fired[p * 125 + t] =
                (sx[p * 16 + oa] * sx[p * 16 + ob]) * sx[p * 16 + oc];
        }
    }
    __syncthreads();

    // ---- Phase 3: dense vectorized copy to global (500 float4) ----
    const float4* f4 = (const float4*)fired;
    float4* o = out4 + cta * OUT_VEC4;
    #pragma unroll
    for (int m = 0; m < 4; m++) {
        const int q = t + m * THREADS;            // 0..499
        if (q < OUT_VEC4) o[q] = f4[q];
    }
}

extern "C" void kernel_launch(void* const* d_in, const int* in_sizes, int n_in,
                              void* d_out, int out_size) {
    const float4* x4 = (const float4*)d_in[0];   // (B,S,15) float32, B*S=32768
    // d_in[1] = active_rules (compile-time structure), d_in[2] = epoch
    float4* out4 = (float4*)d_out;               // (B,S,125) float32

    const int total_pos = in_sizes[0] / 15;      // 32768
    const int n_ctas = total_pos / P_PER_CTA;    // 2048

    rules_fired_kernel<<<n_ctas, THREADS>>>(x4, out4);
}

// round 8
// speedup vs baseline: 1.4676x; 1.4676x over previous
#include <cuda_runtime.h>

// Rules_67619965108887: out[b,s,r] = (a_i*b_j)*c_k, r = i*25+j*5+k,
//   a_i=f(x[i]), b_j=f(x[5+j]), c_k=f(x[10+k]), f(v)=(v==0)?1:v.
// Association (a*b)*c matches jnp.prod ascending order -> bitwise equal.
//
// R8: R7's smem round-trip for the output (STS+bar+LDS+STG.128) was the
// regression. Direct coalesced STG.32 issue cost is trivial (~0.6us chip-wide)
// and L2 absorbs the writes, so store straight from registers:
//   Phase 1: coalesced float4 load of 32 positions -> sx[p][16] (zero->one fix).
//   Phase 2: thread t<125 owns rule r=t. (i,j,k)/offsets computed ONCE.
//            For each of 32 positions: 3 broadcast-friendly LDS (15 words of a
//            position live in 15 distinct banks -> conflict-free) + 2 FMUL +
//            1 coalesced STG.32 (125 consecutive floats per position).
// ONE barrier, no output staging, grid 1024 (~7 CTAs/SM single wave).

constexpr int THREADS   = 128;
constexpr int P_PER_CTA = 32;
constexpr int IN_VEC4   = P_PER_CTA * 15 / 4;     // 120

__global__ __launch_bounds__(THREADS, 12)
void rules_fired_kernel(const float4* __restrict__ x4,
                        float* __restrict__ out) {
    __shared__ float sx[P_PER_CTA * 16];          // 2 KB, [pos][16]

    const int t = threadIdx.x;
    const size_t cta = blockIdx.x;

    // ---- Phase 1: coalesced load of 32 positions (480 floats = 120 float4) ----
    if (t < IN_VEC4) {
        float4 v = x4[cta * IN_VEC4 + t];
        float vals[4] = {v.x, v.y, v.z, v.w};
        const int li0 = t * 4;
        #pragma unroll
        for (int e = 0; e < 4; e++) {
            const int li = li0 + e;               // 0..479
            const int p  = li / 15;
            const int f  = li - p * 15;
            const float w = vals[e];
            sx[p * 16 + f] = (w == 0.0f) ? 1.0f : w;
        }
    }
    __syncthreads();

    // ---- Phase 2: thread owns rule r = t; direct coalesced stores ----
    if (t < 125) {
        const int i  = t / 25;                    // computed ONCE
        const int jj = t - i * 25;
        const int j  = jj / 5;
        const int k  = jj - j * 5;
        const int oa = i;
        const int ob = 5 + j;
        const int oc = 10 + k;

        float* o = out + cta * (size_t)(P_PER_CTA * 125) + t;

        #pragma unroll 8
        for (int p = 0; p < P_PER_CTA; p++) {
            // LDS offsets fold to immediates; in-warp the 3 loads touch at
            // most 15 distinct words, all in distinct banks (stride-16 rows).
            const float r = (sx[p * 16 + oa] * sx[p * 16 + ob]) * sx[p * 16 + oc];
            o[p * 125] = r;                       // 125 consecutive floats/warp-group
        }
    }
}

extern "C" void kernel_launch(void* const* d_in, const int* in_sizes, int n_in,
                              void* d_out, int out_size) {
    const float4* x4 = (const float4*)d_in[0];   // (B,S,15) float32, B*S=32768
    // d_in[1] = active_rules (compile-time structure), d_in[2] = epoch
    float* out = (float*)d_out;                  // (B,S,125) float32

    const int total_pos = in_sizes[0] / 15;      // 32768
    const int n_ctas = total_pos / P_PER_CTA;    // 1024

    rules_fired_kernel<<<n_ctas, THREADS>>>(x4, out);
}